// round 11
// baseline (speedup 1.0000x reference)
#include <cuda_runtime.h>
#include <math.h>

#define BATCH  8
#define NPTS   131072
#define DIM    32
#define NLAB   33
#define KINST  32
#define CHUNK  512
#define CHUNKS (NPTS / CHUNK)        // 256 chunks per batch
#define NBLK   (BATCH * CHUNKS)      // 2048 (power of 2: ticket mask)
#define THREADS 256
#define NWARP   8
#define WPTS    (CHUNK / NWARP)      // 64 points per warp
#define ROWW   (KINST + 1)           // padded row width in finalize

// ---- scratch (no allocations). Zero at module load; fused finalize re-zeros
// ---- at the end of every replay, so each graph replay starts clean.
__device__ float g_sums[BATCH * NLAB * DIM];
__device__ float g_counts[BATCH * NLAB];
__device__ float g_hinge[BATCH * NLAB];
__device__ unsigned g_fin;           // monotonic ticket (never reset)

// Pass 1: per-(b,label) sums + counts. Warp-per-point lane-private SMEM RMW
// (race-free); double-buffered 8-deep load groups; match_any counts.
__global__ void __launch_bounds__(THREADS) k_pass1(const float* __restrict__ emb,
                                                   const int* __restrict__ lab) {
    __shared__ float s_sums[NWARP][NLAB * DIM];
    __shared__ float s_cnt[NWARP][NLAB];
    int tid = threadIdx.x, wid = tid >> 5, lane = tid & 31;

    for (int i = tid; i < NWARP * NLAB * DIM; i += THREADS) (&s_sums[0][0])[i] = 0.f;
    for (int i = tid; i < NWARP * NLAB; i += THREADS)       (&s_cnt[0][0])[i]  = 0.f;
    __syncthreads();

    int b = blockIdx.x / CHUNKS;
    int chunk = blockIdx.x % CHUNKS;
    const float* ebase = emb + ((size_t)b * NPTS + (size_t)chunk * CHUNK) * DIM;
    const int*   lbase = lab + (size_t)b * NPTS + (size_t)chunk * CHUNK;

    float* ws = s_sums[wid];
    float* wc = s_cnt[wid];
    int p0 = wid * WPTS;

    int myl0 = lbase[p0 + lane];                    // labels for points 0..31
    int myl1 = lbase[p0 + 32 + lane];               // labels for points 32..63

    unsigned peers = __match_any_sync(0xffffffffu, myl0);
    if ((__ffs(peers) - 1) == lane) wc[myl0] += (float)__popc(peers);
    peers = __match_any_sync(0xffffffffu, myl1);
    if ((__ffs(peers) - 1) == lane) wc[myl1] += (float)__popc(peers);

    float v[8];
    #pragma unroll
    for (int i = 0; i < 8; i++)                     // prologue: group 0 in flight
        v[i] = ebase[(size_t)(p0 + i) * DIM + lane];

    #pragma unroll
    for (int gix = 0; gix < 8; gix++) {             // 8 groups of 8 points
        float vn[8];
        if (gix < 7) {
            #pragma unroll
            for (int i = 0; i < 8; i++)             // next group overlaps RMW
                vn[i] = ebase[(size_t)(p0 + (gix + 1) * 8 + i) * DIM + lane];
        }
        #pragma unroll
        for (int i = 0; i < 8; i++) {
            int pi = gix * 8 + i;
            int l = (pi < 32) ? __shfl_sync(0xffffffffu, myl0, pi)
                              : __shfl_sync(0xffffffffu, myl1, pi - 32);
            ws[l * DIM + lane] += v[i];             // lane-private: no race
        }
        if (gix < 7) {
            #pragma unroll
            for (int i = 0; i < 8; i++) v[i] = vn[i];
        }
    }
    __syncthreads();

    for (int i = tid; i < NLAB * DIM; i += THREADS) {
        float s = 0.f;
        #pragma unroll
        for (int w = 0; w < NWARP; w++) s += s_sums[w][i];
        atomicAdd(&g_sums[b * NLAB * DIM + i], s);
    }
    for (int i = tid; i < NLAB; i += THREADS) {
        float s = 0.f;
        #pragma unroll
        for (int w = 0; w < NWARP; w++) s += s_cnt[w][i];
        atomicAdd(&g_counts[b * NLAB + i], s);
    }
}

// Pass 3 + fused finalize. __launch_bounds__(256, 6) caps regs at 42: the
// mainloop (37 regs standalone) fits cleanly -> 6 blocks/SM; the cold
// finalize path (runs once, one block) spills to local -- acceptable.
// Pass3: reversed block order (L2 reuse), float4 quartets, 8 LDG.128 staged,
// 3-deep shfl reduce, group-private hinge replicas. Last block (monotonic
// ticket) finalizes and re-zeros accumulators for the next graph replay.
__global__ void __launch_bounds__(THREADS, 6) k_pass3(const float* __restrict__ emb,
                                                      const int* __restrict__ lab,
                                                      float* __restrict__ out) {
    // union: pass3 mean(1056)+hinge(1056) | finalize matrix 8*1056 + res 16
    __shared__ __align__(16) float s_u[BATCH * DIM * ROWW + 16];
    __shared__ unsigned s_last;
    int tid = threadIdx.x, wid = tid >> 5, lane = tid & 31;
    int g = lane >> 3, s = lane & 7;

    {
        float* s_mean = s_u;                            // 1056
        float (*s_h)[NLAB] = (float (*)[NLAB])(s_u + NLAB * DIM);  // 32 x 33

        int idx = NBLK - 1 - blockIdx.x;                // reversed for L2 reuse
        int b = idx / CHUNKS;
        int chunk = idx % CHUNKS;

        for (int i = tid; i < NLAB * DIM; i += THREADS) {
            float c = g_counts[b * NLAB + i / DIM];
            s_mean[i] = g_sums[b * NLAB * DIM + i] / fmaxf(c, 1.f);
        }
        for (int i = tid; i < NWARP * 4 * NLAB; i += THREADS) (&s_h[0][0])[i] = 0.f;
        __syncthreads();

        const float4* e4 = (const float4*)(emb + ((size_t)b * NPTS + (size_t)chunk * CHUNK) * DIM);
        const int*    lbase = lab + (size_t)b * NPTS + (size_t)chunk * CHUNK;
        const float4* m4 = (const float4*)s_mean;
        float* wh = s_h[wid * 4 + g];
        int p0 = wid * WPTS;

        for (int w = 0; w < WPTS; w += 32) {
            int myl = lbase[p0 + w + lane];
            float4 v[8]; int lq[8];
            #pragma unroll
            for (int q = 0; q < 8; q++) {               // 8 LDG.128 in flight
                int p = p0 + w + q * 4 + g;
                v[q] = e4[(size_t)p * 8 + s];           // 512B/warp contiguous
                lq[q] = __shfl_sync(0xffffffffu, myl, q * 4 + g);
            }
            #pragma unroll
            for (int q = 0; q < 8; q++) {
                float4 m = m4[lq[q] * 8 + s];
                float dx = v[q].x - m.x, dy = v[q].y - m.y;
                float dz = v[q].z - m.z, dw = v[q].w - m.w;
                float sq = dx * dx + dy * dy + dz * dz + dw * dw;
                sq += __shfl_xor_sync(0xffffffffu, sq, 1);
                sq += __shfl_xor_sync(0xffffffffu, sq, 2);
                sq += __shfl_xor_sync(0xffffffffu, sq, 4);
                if (s == 0) {
                    float dist = sqrtf(sq + 1e-24f);
                    wh[lq[q]] += fmaxf(dist - 0.1f, 0.f);
                }
            }
        }
        __syncthreads();

        for (int i = tid; i < NLAB; i += THREADS) {
            float acc = 0.f;
            #pragma unroll
            for (int r = 0; r < NWARP * 4; r++) acc += s_h[r][i];
            atomicAdd(&g_hinge[b * NLAB + i], acc);
        }
    }

    // ---- completion ticket: last block of this replay runs the finalize ----
    __threadfence();
    __syncthreads();
    if (tid == 0) {
        unsigned t = atomicAdd(&g_fin, 1u);
        s_last = ((t & (NBLK - 1u)) == (NBLK - 1u)) ? 1u : 0u;
    }
    __syncthreads();
    if (!s_last) return;
    __threadfence();
    __syncthreads();                                    // s_u reuse barrier

    // ================= FINALIZE (warp = batch; cold path, may spill) ========
    {
        int b = wid;
        float* sm = s_u + b * (DIM * ROWW);             // [dim][k] padded rows
        float* s_res = s_u + BATCH * DIM * ROWW;        // 16 floats

        float cvec = g_counts[b * NLAB + 1 + lane];     // lane <-> label lane+1
        float pres = (cvec > 0.f) ? 1.f : 0.f;
        float hs   = g_hinge[b * NLAB + 1 + lane];

        #pragma unroll
        for (int k = 0; k < KINST; k++) {
            float c = __shfl_sync(0xffffffffu, cvec, k);
            sm[lane * ROWW + k] =
                g_sums[b * NLAB * DIM + (k + 1) * DIM + lane] / fmaxf(c, 1.f);
        }
        __syncwarp();

        float nrm = 0.f;                                // lane = instance k
        #pragma unroll
        for (int d = 0; d < DIM; d++) { float x = sm[d * ROWW + lane]; nrm += x * x; }
        float rinv = 1.f / fmaxf(sqrtf(nrm), 1e-12f);
        #pragma unroll
        for (int d = 0; d < DIM; d++) sm[d * ROWW + lane] *= rinv;
        __syncwarp();

        float hp = 0.f, pm = 0.f;
        for (int i = 0; i < KINST; i++) {
            float pi = __shfl_sync(0xffffffffu, pres, i);
            float mask = (lane > i) ? pi * pres : 0.f;
            float sq = 0.f;
            #pragma unroll
            for (int d = 0; d < DIM; d++) {
                float diff = sm[d * ROWW + i] - sm[d * ROWW + lane];
                sq += diff * diff;
            }
            hp += fmaxf(1.0f - sqrtf(sq + 1e-24f), 0.f) * mask;  // 2*DELTA_D=1
            pm += mask;
        }

        float seg = hs / fmaxf(cvec, 1.f);
        float segsum = seg, ninst = pres;
        #pragma unroll
        for (int o = 16; o; o >>= 1) {
            segsum += __shfl_xor_sync(0xffffffffu, segsum, o);
            ninst  += __shfl_xor_sync(0xffffffffu, ninst, o);
            hp     += __shfl_xor_sync(0xffffffffu, hp, o);
            pm     += __shfl_xor_sync(0xffffffffu, pm, o);
        }
        if (lane == 0) {
            s_res[b * 2]     = segsum / (ninst + 1e-6f);
            s_res[b * 2 + 1] = (ninst > 1.f) ? hp / (pm + 1e-6f) : 0.f;
        }
        __syncthreads();

        if (tid < 32) {
            float pull = (lane < BATCH) ? s_res[lane * 2]     : 0.f;
            float push = (lane < BATCH) ? s_res[lane * 2 + 1] : 0.f;
            #pragma unroll
            for (int o = 4; o; o >>= 1) {
                pull += __shfl_xor_sync(0xffffffffu, pull, o);
                push += __shfl_xor_sync(0xffffffffu, push, o);
            }
            if (lane == 0) {
                pull *= (1.0f / BATCH);
                push *= (1.0f / BATCH);
                out[0] = pull + push;
                out[1] = pull;
                out[2] = push;
            }
        }
        __syncthreads();

        // re-zero accumulators for the next replay (out already written)
        for (int i = tid; i < BATCH * NLAB * DIM; i += THREADS) g_sums[i] = 0.f;
        for (int i = tid; i < BATCH * NLAB; i += THREADS) {
            g_counts[i] = 0.f;
            g_hinge[i]  = 0.f;
        }
    }
}

extern "C" void kernel_launch(void* const* d_in, const int* in_sizes, int n_in,
                              void* d_out, int out_size) {
    const float* emb = (const float*)d_in[0];
    const int*   lab = (const int*)d_in[1];
    float* out = (float*)d_out;
    (void)in_sizes; (void)n_in; (void)out_size;

    k_pass1<<<NBLK, THREADS>>>(emb, lab);
    k_pass3<<<NBLK, THREADS>>>(emb, lab, out);
}

// round 12
// speedup vs baseline: 1.4610x; 1.4610x over previous
#include <cuda_runtime.h>
#include <math.h>

#define BATCH  8
#define NPTS   131072
#define DIM    32
#define NLAB   33
#define KINST  32
#define CHUNK  512
#define CHUNKS (NPTS / CHUNK)        // 256 chunks per batch per pass
#define THREADS 256
#define NWARP   8
#define WPTS    (CHUNK / NWARP)      // 64 points per warp
#define P1BLOCKS (BATCH * CHUNKS)    // 2048
#define GRID     (2 * P1BLOCKS)      // 4096
#define ROWW   (KINST + 1)

// ---- scratch (no allocations). Zero at module load; k_final re-zeros the
// ---- accumulators each replay. Tickets are monotonic (never reset).
__device__ float g_sums[BATCH * NLAB * DIM];
__device__ float g_counts[BATCH * NLAB];
__device__ float g_hinge[BATCH * NLAB];
__device__ float g_pp[BATCH * 2];
__device__ unsigned g_p1done[BATCH];   // pass1 block completions per batch
__device__ unsigned g_p3tick[BATCH];   // pass3 start tickets per batch
__device__ unsigned g_fin;             // finalize ticket

// Fused pass1 + gated pass3 (NO finalize code here -- keeps registers sane).
// Blocks 0..2047: pass1 (v[8] staging, 35-reg shape). Blocks 2048..4095:
// pass3 for batch b, gated on pass1(b) completion via monotonic epochs, so it
// reads batch b's 16.5MB while it is genuinely L2-hot.
__global__ void __launch_bounds__(THREADS) k_fused(const float* __restrict__ emb,
                                                   const int* __restrict__ lab) {
    // union: pass1 sums(8448)+cnt(264) | pass3 mean(1056)+hinge(1056)
    __shared__ __align__(16) float s_buf[NWARP * NLAB * DIM + NWARP * NLAB];
    int tid = threadIdx.x, wid = tid >> 5, lane = tid & 31;

    if (blockIdx.x < P1BLOCKS) {
        // ---------------- PASS 1 ----------------
        int b = blockIdx.x / CHUNKS;                // ascending: batch 0 first
        int chunk = blockIdx.x % CHUNKS;
        float (*s_sums)[NLAB * DIM] = (float (*)[NLAB * DIM])s_buf;
        float (*s_cnt)[NLAB] = (float (*)[NLAB])(s_buf + NWARP * NLAB * DIM);

        for (int i = tid; i < NWARP * NLAB * DIM; i += THREADS) (&s_sums[0][0])[i] = 0.f;
        for (int i = tid; i < NWARP * NLAB; i += THREADS)       (&s_cnt[0][0])[i]  = 0.f;
        __syncthreads();

        const float* ebase = emb + ((size_t)b * NPTS + (size_t)chunk * CHUNK) * DIM;
        const int*   lbase = lab + (size_t)b * NPTS + (size_t)chunk * CHUNK;
        float* ws = s_sums[wid];
        float* wc = s_cnt[wid];
        int p0 = wid * WPTS;

        for (int w = 0; w < WPTS; w += 32) {
            int myl = lbase[p0 + w + lane];                 // coalesced labels
            unsigned peers = __match_any_sync(0xffffffffu, myl);
            if ((__ffs(peers) - 1) == lane)
                wc[myl] += (float)__popc(peers);            // distinct addrs
            #pragma unroll
            for (int h = 0; h < 32; h += 8) {
                float v[8];
                #pragma unroll
                for (int i = 0; i < 8; i++)                 // 8 LDGs in flight
                    v[i] = ebase[(size_t)(p0 + w + h + i) * DIM + lane];
                #pragma unroll
                for (int i = 0; i < 8; i++) {
                    int l = __shfl_sync(0xffffffffu, myl, h + i);
                    ws[l * DIM + lane] += v[i];             // lane-private
                }
            }
        }
        __syncthreads();

        for (int i = tid; i < NLAB * DIM; i += THREADS) {
            float s = 0.f;
            #pragma unroll
            for (int w = 0; w < NWARP; w++) s += s_sums[w][i];
            atomicAdd(&g_sums[b * NLAB * DIM + i], s);
        }
        for (int i = tid; i < NLAB; i += THREADS) {
            float s = 0.f;
            #pragma unroll
            for (int w = 0; w < NWARP; w++) s += s_cnt[w][i];
            atomicAdd(&g_counts[b * NLAB + i], s);
        }
        __threadfence();                                    // release sums/counts
        __syncthreads();
        if (tid == 0) atomicAdd(&g_p1done[b], 1u);
        return;
    }

    // ---------------- PASS 3 (gated per batch) ----------------
    int idx = blockIdx.x - P1BLOCKS;
    int b = idx / CHUNKS;                                   // ascending
    int chunk = idx % CHUNKS;

    if (tid == 0) {
        unsigned e = atomicAdd(&g_p3tick[b], 1u) >> 8;      // 256 p3 blocks/batch
        unsigned need = (e + 1u) << 8;                      // (epoch+1)*256
        while (atomicAdd(&g_p1done[b], 0u) < need) __nanosleep(64);
    }
    __syncthreads();

    float* s_mean = s_buf;                                  // 1056
    float (*s_h)[NLAB] = (float (*)[NLAB])(s_buf + NLAB * DIM);  // 32 x 33
    int g = lane >> 3, s = lane & 7;

    for (int i = tid; i < NLAB * DIM; i += THREADS) {
        float c = g_counts[b * NLAB + i / DIM];
        s_mean[i] = g_sums[b * NLAB * DIM + i] / fmaxf(c, 1.f);
    }
    for (int i = tid; i < NWARP * 4 * NLAB; i += THREADS) (&s_h[0][0])[i] = 0.f;
    __syncthreads();

    const float4* e4 = (const float4*)(emb + ((size_t)b * NPTS + (size_t)chunk * CHUNK) * DIM);
    const int*    lbase = lab + (size_t)b * NPTS + (size_t)chunk * CHUNK;
    const float4* m4 = (const float4*)s_mean;
    float* wh = s_h[wid * 4 + g];
    int p0 = wid * WPTS;

    for (int w = 0; w < WPTS; w += 32) {
        int myl = lbase[p0 + w + lane];
        float4 v[8]; int lq[8];
        #pragma unroll
        for (int q = 0; q < 8; q++) {                       // 8 LDG.128 in flight
            int p = p0 + w + q * 4 + g;
            v[q] = e4[(size_t)p * 8 + s];                   // 512B/warp contiguous
            lq[q] = __shfl_sync(0xffffffffu, myl, q * 4 + g);
        }
        #pragma unroll
        for (int q = 0; q < 8; q++) {
            float4 m = m4[lq[q] * 8 + s];
            float dx = v[q].x - m.x, dy = v[q].y - m.y;
            float dz = v[q].z - m.z, dw = v[q].w - m.w;
            float sq = dx * dx + dy * dy + dz * dz + dw * dw;
            sq += __shfl_xor_sync(0xffffffffu, sq, 1);
            sq += __shfl_xor_sync(0xffffffffu, sq, 2);
            sq += __shfl_xor_sync(0xffffffffu, sq, 4);
            if (s == 0) {
                float dist = sqrtf(sq + 1e-24f);
                wh[lq[q]] += fmaxf(dist - 0.1f, 0.f);       // group-private
            }
        }
    }
    __syncthreads();

    for (int i = tid; i < NLAB; i += THREADS) {
        float acc = 0.f;
        #pragma unroll
        for (int r = 0; r < NWARP * 4; r++) acc += s_h[r][i];
        atomicAdd(&g_hinge[b * NLAB + i], acc);
    }
}

// Finalize: grid=8, block b computes pull_b/push_b, RE-ZEROS its batch slice
// for the next replay, then block 0 reduces via the monotonic ticket barrier.
__global__ void __launch_bounds__(THREADS) k_final(float* __restrict__ out) {
    __shared__ __align__(16) float sm[DIM * ROWW];
    __shared__ float s_pres[KINST];
    __shared__ float s_hp[NWARP], s_pm[NWARP];
    __shared__ unsigned s_target;
    int tid = threadIdx.x, wid = tid >> 5, lane = tid & 31;
    int b = blockIdx.x;

    // Phase A: 8 warps load means in parallel (warp w -> instances w*4..+3)
    #pragma unroll
    for (int i = 0; i < 4; i++) {
        int k = wid * 4 + i;
        float c = g_counts[b * NLAB + 1 + k];
        float m = g_sums[b * NLAB * DIM + (k + 1) * DIM + lane] / fmaxf(c, 1.f);
        sm[lane * ROWW + k] = m;                            // lane = dim
        if (lane == 0) s_pres[k] = (c > 0.f) ? 1.f : 0.f;
    }
    __syncthreads();

    // Phase B: warp 0 normalizes (lane = instance k, serial over dims)
    if (wid == 0) {
        float nrm = 0.f;
        #pragma unroll
        for (int d = 0; d < DIM; d++) { float x = sm[d * ROWW + lane]; nrm += x * x; }
        float rinv = 1.f / fmaxf(sqrtf(nrm), 1e-12f);
        #pragma unroll
        for (int d = 0; d < DIM; d++) sm[d * ROWW + lane] *= rinv;
    }
    __syncthreads();

    // Phase C: pair loop split over 8 warps
    float pres = s_pres[lane];
    float mc[DIM];
    #pragma unroll
    for (int d = 0; d < DIM; d++) mc[d] = sm[d * ROWW + lane];

    float hp = 0.f, pm = 0.f;
    #pragma unroll
    for (int ii = 0; ii < 4; ii++) {
        int i = wid * 4 + ii;
        float pi = s_pres[i];
        float mask = (lane > i) ? pi * pres : 0.f;
        float sq = 0.f;
        #pragma unroll
        for (int d = 0; d < DIM; d++) {
            float diff = sm[d * ROWW + i] - mc[d];
            sq += diff * diff;
        }
        hp += fmaxf(1.0f - sqrtf(sq + 1e-24f), 0.f) * mask;  // 2*DELTA_D = 1
        pm += mask;
    }
    #pragma unroll
    for (int o = 16; o; o >>= 1) {
        hp += __shfl_xor_sync(0xffffffffu, hp, o);
        pm += __shfl_xor_sync(0xffffffffu, pm, o);
    }
    if (lane == 0) { s_hp[wid] = hp; s_pm[wid] = pm; }
    __syncthreads();

    if (wid == 0) {
        float c  = g_counts[b * NLAB + 1 + lane];
        float hs = g_hinge[b * NLAB + 1 + lane];
        float seg  = hs / fmaxf(c, 1.f);
        float pr   = (c > 0.f) ? 1.f : 0.f;
        float segsum = seg, ninst = pr;
        float hps = (lane < NWARP) ? s_hp[lane] : 0.f;
        float pms = (lane < NWARP) ? s_pm[lane] : 0.f;
        #pragma unroll
        for (int o = 16; o; o >>= 1) {
            segsum += __shfl_xor_sync(0xffffffffu, segsum, o);
            ninst  += __shfl_xor_sync(0xffffffffu, ninst, o);
            hps    += __shfl_xor_sync(0xffffffffu, hps, o);
            pms    += __shfl_xor_sync(0xffffffffu, pms, o);
        }
        if (lane == 0) {
            __stcg(&g_pp[b * 2],     segsum / (ninst + 1e-6f));
            __stcg(&g_pp[b * 2 + 1], (ninst > 1.f) ? hps / (pms + 1e-6f) : 0.f);
        }
    }
    __syncthreads();

    // re-zero this batch's accumulator slice for the next replay
    for (int i = tid; i < NLAB * DIM; i += THREADS) g_sums[b * NLAB * DIM + i] = 0.f;
    for (int i = tid; i < NLAB; i += THREADS) {
        g_counts[b * NLAB + i] = 0.f;
        g_hinge[b * NLAB + i]  = 0.f;
    }

    // monotonic ticket barrier (8 blocks always co-resident)
    __threadfence();
    __syncthreads();
    if (tid == 0) {
        unsigned t = atomicAdd(&g_fin, 1u);
        if (b == 0) s_target = (t / 8u + 1u) * 8u;
    }
    __syncthreads();

    if (b == 0 && tid == 0) {
        unsigned target = s_target;
        while (atomicAdd(&g_fin, 0u) < target) __nanosleep(128);
        __threadfence();
        float pull = 0.f, push = 0.f;
        #pragma unroll
        for (int bb = 0; bb < BATCH; bb++) {
            pull += __ldcg(&g_pp[bb * 2]);
            push += __ldcg(&g_pp[bb * 2 + 1]);
        }
        pull *= (1.0f / BATCH);
        push *= (1.0f / BATCH);
        out[0] = pull + push;
        out[1] = pull;
        out[2] = push;
    }
}

extern "C" void kernel_launch(void* const* d_in, const int* in_sizes, int n_in,
                              void* d_out, int out_size) {
    const float* emb = (const float*)d_in[0];
    const int*   lab = (const int*)d_in[1];
    float* out = (float*)d_out;
    (void)in_sizes; (void)n_in; (void)out_size;

    k_fused<<<GRID, THREADS>>>(emb, lab);
    k_final<<<BATCH, THREADS>>>(out);
}

// round 13
// speedup vs baseline: 1.6036x; 1.0976x over previous
#include <cuda_runtime.h>
#include <math.h>

#define BATCH  8
#define NPTS   131072
#define DIM    32
#define NLAB   33
#define KINST  32
#define CHUNK  512
#define CHUNKS (NPTS / CHUNK)        // 256 chunks per batch
#define NBLK   (BATCH * CHUNKS)      // 2048
#define THREADS 256
#define NWARP   8
#define WPTS    (CHUNK / NWARP)      // 64 points per warp
#define ROWW   (KINST + 1)

// ---- scratch (no allocations). Zero at module load; k_final re-zeros its
// ---- batch slice every replay, so each graph replay starts clean.
__device__ float g_sums[BATCH * NLAB * DIM];
__device__ float g_counts[BATCH * NLAB];
__device__ float g_hinge[BATCH * NLAB];

// Pass 1: per-(b,label) sums + counts. Warp-per-point lane-private SMEM RMW
// (race-free); double-buffered 8-deep load groups; match_any counts.
// Block 0 also zero-initializes out[] (harness poisons it to 0xAA) so that
// k_final can accumulate into it with atomics.
__global__ void __launch_bounds__(THREADS) k_pass1(const float* __restrict__ emb,
                                                   const int* __restrict__ lab,
                                                   float* __restrict__ out) {
    __shared__ float s_sums[NWARP][NLAB * DIM];
    __shared__ float s_cnt[NWARP][NLAB];
    int tid = threadIdx.x, wid = tid >> 5, lane = tid & 31;

    if (blockIdx.x == 0 && tid < 4) out[tid] = 0.f;   // reset output accumulators

    for (int i = tid; i < NWARP * NLAB * DIM; i += THREADS) (&s_sums[0][0])[i] = 0.f;
    for (int i = tid; i < NWARP * NLAB; i += THREADS)       (&s_cnt[0][0])[i]  = 0.f;
    __syncthreads();

    int b = blockIdx.x / CHUNKS;
    int chunk = blockIdx.x % CHUNKS;
    const float* ebase = emb + ((size_t)b * NPTS + (size_t)chunk * CHUNK) * DIM;
    const int*   lbase = lab + (size_t)b * NPTS + (size_t)chunk * CHUNK;

    float* ws = s_sums[wid];
    float* wc = s_cnt[wid];
    int p0 = wid * WPTS;

    int myl0 = lbase[p0 + lane];                    // labels for points 0..31
    int myl1 = lbase[p0 + 32 + lane];               // labels for points 32..63

    unsigned peers = __match_any_sync(0xffffffffu, myl0);
    if ((__ffs(peers) - 1) == lane) wc[myl0] += (float)__popc(peers);
    peers = __match_any_sync(0xffffffffu, myl1);
    if ((__ffs(peers) - 1) == lane) wc[myl1] += (float)__popc(peers);

    float v[8];
    #pragma unroll
    for (int i = 0; i < 8; i++)                     // prologue: group 0 in flight
        v[i] = ebase[(size_t)(p0 + i) * DIM + lane];

    #pragma unroll
    for (int gix = 0; gix < 8; gix++) {             // 8 groups of 8 points
        float vn[8];
        if (gix < 7) {
            #pragma unroll
            for (int i = 0; i < 8; i++)             // next group overlaps RMW
                vn[i] = ebase[(size_t)(p0 + (gix + 1) * 8 + i) * DIM + lane];
        }
        #pragma unroll
        for (int i = 0; i < 8; i++) {
            int pi = gix * 8 + i;
            int l = (pi < 32) ? __shfl_sync(0xffffffffu, myl0, pi)
                              : __shfl_sync(0xffffffffu, myl1, pi - 32);
            ws[l * DIM + lane] += v[i];             // lane-private: no race
        }
        if (gix < 7) {
            #pragma unroll
            for (int i = 0; i < 8; i++) v[i] = vn[i];
        }
    }
    __syncthreads();

    for (int i = tid; i < NLAB * DIM; i += THREADS) {
        float s = 0.f;
        #pragma unroll
        for (int w = 0; w < NWARP; w++) s += s_sums[w][i];
        atomicAdd(&g_sums[b * NLAB * DIM + i], s);
    }
    for (int i = tid; i < NLAB; i += THREADS) {
        float s = 0.f;
        #pragma unroll
        for (int w = 0; w < NWARP; w++) s += s_cnt[w][i];
        atomicAdd(&g_counts[b * NLAB + i], s);
    }
}

// Pass 3: hinge(||x - mean[label]|| - 0.1), segment-summed per (b,label).
// REVERSED block order (reads pass1's L2-resident tail first). float4
// quartets, 8 LDG.128 staged, 3-deep shfl reduce, group-private replicas.
__global__ void __launch_bounds__(THREADS) k_pass3(const float* __restrict__ emb,
                                                   const int* __restrict__ lab) {
    __shared__ __align__(16) float s_mean[NLAB * DIM];
    __shared__ float s_h[NWARP * 4][NLAB];
    int tid = threadIdx.x, wid = tid >> 5, lane = tid & 31;
    int g = lane >> 3, s = lane & 7;

    int idx = NBLK - 1 - blockIdx.x;                // reversed for L2 reuse
    int b = idx / CHUNKS;
    int chunk = idx % CHUNKS;

    for (int i = tid; i < NLAB * DIM; i += THREADS) {
        float c = g_counts[b * NLAB + i / DIM];
        s_mean[i] = g_sums[b * NLAB * DIM + i] / fmaxf(c, 1.f);
    }
    for (int i = tid; i < NWARP * 4 * NLAB; i += THREADS) (&s_h[0][0])[i] = 0.f;
    __syncthreads();

    const float4* e4 = (const float4*)(emb + ((size_t)b * NPTS + (size_t)chunk * CHUNK) * DIM);
    const int*    lbase = lab + (size_t)b * NPTS + (size_t)chunk * CHUNK;
    const float4* m4 = (const float4*)s_mean;
    float* wh = s_h[wid * 4 + g];
    int p0 = wid * WPTS;

    for (int w = 0; w < WPTS; w += 32) {
        int myl = lbase[p0 + w + lane];
        float4 v[8]; int lq[8];
        #pragma unroll
        for (int q = 0; q < 8; q++) {               // 8 LDG.128 in flight
            int p = p0 + w + q * 4 + g;
            v[q] = e4[(size_t)p * 8 + s];           // 512B/warp contiguous
            lq[q] = __shfl_sync(0xffffffffu, myl, q * 4 + g);
        }
        #pragma unroll
        for (int q = 0; q < 8; q++) {
            float4 m = m4[lq[q] * 8 + s];
            float dx = v[q].x - m.x, dy = v[q].y - m.y;
            float dz = v[q].z - m.z, dw = v[q].w - m.w;
            float sq = dx * dx + dy * dy + dz * dz + dw * dw;
            sq += __shfl_xor_sync(0xffffffffu, sq, 1);
            sq += __shfl_xor_sync(0xffffffffu, sq, 2);
            sq += __shfl_xor_sync(0xffffffffu, sq, 4);
            if (s == 0) {
                float dist = sqrtf(sq + 1e-24f);
                wh[lq[q]] += fmaxf(dist - 0.1f, 0.f);
            }
        }
    }
    __syncthreads();

    for (int i = tid; i < NLAB; i += THREADS) {
        float acc = 0.f;
        #pragma unroll
        for (int r = 0; r < NWARP * 4; r++) acc += s_h[r][i];
        atomicAdd(&g_hinge[b * NLAB + i], acc);
    }
}

// Finalize: grid=8, block b computes pull_b/push_b and atomically accumulates
// into out[] (pre-zeroed by pass1) -- NO cross-block spin, NO serial gather.
// Also re-zeros its batch's accumulator slice for the next replay.
__global__ void __launch_bounds__(THREADS) k_final(float* __restrict__ out) {
    __shared__ __align__(16) float sm[DIM * ROWW];
    __shared__ float s_pres[KINST];
    __shared__ float s_hp[NWARP], s_pm[NWARP];
    int tid = threadIdx.x, wid = tid >> 5, lane = tid & 31;
    int b = blockIdx.x;

    // Phase A: 8 warps load means in parallel (warp w -> instances w*4..+3)
    #pragma unroll
    for (int i = 0; i < 4; i++) {
        int k = wid * 4 + i;
        float c = g_counts[b * NLAB + 1 + k];
        float m = g_sums[b * NLAB * DIM + (k + 1) * DIM + lane] / fmaxf(c, 1.f);
        sm[lane * ROWW + k] = m;                    // lane = dim
        if (lane == 0) s_pres[k] = (c > 0.f) ? 1.f : 0.f;
    }
    __syncthreads();

    // Phase B: warp 0 normalizes (lane = instance k, serial over dims)
    if (wid == 0) {
        float nrm = 0.f;
        #pragma unroll
        for (int d = 0; d < DIM; d++) { float x = sm[d * ROWW + lane]; nrm += x * x; }
        float rinv = 1.f / fmaxf(sqrtf(nrm), 1e-12f);
        #pragma unroll
        for (int d = 0; d < DIM; d++) sm[d * ROWW + lane] *= rinv;
    }
    __syncthreads();

    // Phase C: pair loop split over 8 warps
    float pres = s_pres[lane];
    float mc[DIM];
    #pragma unroll
    for (int d = 0; d < DIM; d++) mc[d] = sm[d * ROWW + lane];

    float hp = 0.f, pm = 0.f;
    #pragma unroll
    for (int ii = 0; ii < 4; ii++) {
        int i = wid * 4 + ii;
        float pi = s_pres[i];
        float mask = (lane > i) ? pi * pres : 0.f;
        float sq = 0.f;
        #pragma unroll
        for (int d = 0; d < DIM; d++) {
            float diff = sm[d * ROWW + i] - mc[d];
            sq += diff * diff;
        }
        hp += fmaxf(1.0f - sqrtf(sq + 1e-24f), 0.f) * mask;  // 2*DELTA_D = 1
        pm += mask;
    }
    #pragma unroll
    for (int o = 16; o; o >>= 1) {
        hp += __shfl_xor_sync(0xffffffffu, hp, o);
        pm += __shfl_xor_sync(0xffffffffu, pm, o);
    }
    if (lane == 0) { s_hp[wid] = hp; s_pm[wid] = pm; }
    __syncthreads();

    if (wid == 0) {
        float c  = g_counts[b * NLAB + 1 + lane];
        float hs = g_hinge[b * NLAB + 1 + lane];
        float seg  = hs / fmaxf(c, 1.f);
        float pr   = (c > 0.f) ? 1.f : 0.f;
        float segsum = seg, ninst = pr;
        float hps = (lane < NWARP) ? s_hp[lane] : 0.f;
        float pms = (lane < NWARP) ? s_pm[lane] : 0.f;
        #pragma unroll
        for (int o = 16; o; o >>= 1) {
            segsum += __shfl_xor_sync(0xffffffffu, segsum, o);
            ninst  += __shfl_xor_sync(0xffffffffu, ninst, o);
            hps    += __shfl_xor_sync(0xffffffffu, hps, o);
            pms    += __shfl_xor_sync(0xffffffffu, pms, o);
        }
        if (lane == 0) {
            float pull_b = segsum / (ninst + 1e-6f) * (1.0f / BATCH);
            float push_b = ((ninst > 1.f) ? hps / (pms + 1e-6f) : 0.f) * (1.0f / BATCH);
            atomicAdd(&out[0], pull_b + push_b);
            atomicAdd(&out[1], pull_b);
            atomicAdd(&out[2], push_b);
        }
    }

    // re-zero this batch's accumulator slice for the next replay
    for (int i = tid; i < NLAB * DIM; i += THREADS) g_sums[b * NLAB * DIM + i] = 0.f;
    for (int i = tid; i < NLAB; i += THREADS) {
        g_counts[b * NLAB + i] = 0.f;
        g_hinge[b * NLAB + i]  = 0.f;
    }
}

extern "C" void kernel_launch(void* const* d_in, const int* in_sizes, int n_in,
                              void* d_out, int out_size) {
    const float* emb = (const float*)d_in[0];
    const int*   lab = (const int*)d_in[1];
    float* out = (float*)d_out;
    (void)in_sizes; (void)n_in; (void)out_size;

    k_pass1<<<NBLK, THREADS>>>(emb, lab, out);
    k_pass3<<<NBLK, THREADS>>>(emb, lab);
    k_final<<<BATCH, THREADS>>>(out);
}